// round 15
// baseline (speedup 1.0000x reference)
#include <cuda_runtime.h>
#include <cuda_bf16.h>
#include <math.h>
#include <stdint.h>

#define Bx  32
#define Wt  256
#define IND 4096
#define Hd  1024
#define Zd  100
#define Dd  100
#define G3  3072
#define ZH  1124
#define NHB 128
#define NZB 13
#define NGW 155
#define NCTA (NHB + NZB + NGW)       // 296
#define HB  (Hd * Bx)
#define NSLOT 16

// ---------------- f32x2 packed-FMA helpers (z-pipeline) ----------------
__device__ __forceinline__ void fma2(unsigned long long& d, unsigned long long a, unsigned long long b) {
    asm("fma.rn.f32x2 %0, %1, %2, %0;" : "+l"(d) : "l"(a), "l"(b));
}
__device__ __forceinline__ float2 unpack2(unsigned long long v) {
    float2 r;
    asm("mov.b64 {%0, %1}, %2;" : "=f"(r.x), "=f"(r.y) : "l"(v));
    return r;
}

// ---------------- L2-coherent load/store + sync primitives ----------------
__device__ __forceinline__ ulonglong2 ldcg_u2(const void* p) {
    ulonglong2 v;
    asm volatile("ld.global.cg.v2.u64 {%0,%1},[%2];" : "=l"(v.x), "=l"(v.y) : "l"(p));
    return v;
}
__device__ __forceinline__ float ldcg_f(const float* p) {
    float v; asm volatile("ld.global.cg.f32 %0,[%1];" : "=f"(v) : "l"(p)); return v;
}
__device__ __forceinline__ void stcg_f(float* p, float v) {
    asm volatile("st.global.cg.f32 [%0],%1;" :: "l"(p), "f"(v));
}
__device__ __forceinline__ void stcg_u16(void* p, unsigned short v) {
    asm volatile("st.global.cg.u16 [%0],%1;" :: "l"(p), "h"(v));
}
__device__ __forceinline__ void arrive(unsigned* c) {
    asm volatile("red.release.gpu.global.add.u32 [%0],%1;" :: "l"(c), "r"(1u) : "memory");
}
__device__ __forceinline__ void wait_ge(const unsigned* c, unsigned target) {
    unsigned v;
    do {
        asm volatile("ld.acquire.gpu.global.u32 %0,[%1];" : "=r"(v) : "l"(c) : "memory");
    } while ((int)(v - target) < 0);
}

// ---------------- mma.sync helpers ----------------
__device__ __forceinline__ uint32_t smem_u32(const void* p) {
    uint32_t a;
    asm("{ .reg .u64 t; cvta.to.shared.u64 t, %1; cvt.u32.u64 %0, t; }" : "=r"(a) : "l"(p));
    return a;
}
__device__ __forceinline__ void ldsm4(uint32_t* r, uint32_t addr) {
    asm volatile("ldmatrix.sync.aligned.m8n8.x4.shared.b16 {%0,%1,%2,%3},[%4];"
                 : "=r"(r[0]), "=r"(r[1]), "=r"(r[2]), "=r"(r[3]) : "r"(addr));
}
__device__ __forceinline__ void mma16816(float* c, const uint32_t* a, const uint32_t* b) {
    asm volatile("mma.sync.aligned.m16n8k16.row.col.f32.bf16.bf16.f32 "
                 "{%0,%1,%2,%3},{%4,%5,%6,%7},{%8,%9},{%0,%1,%2,%3};"
                 : "+f"(c[0]), "+f"(c[1]), "+f"(c[2]), "+f"(c[3])
                 : "r"(a[0]), "r"(a[1]), "r"(a[2]), "r"(a[3]), "r"(b[0]), "r"(b[1]));
}
__device__ __forceinline__ void cp_async16(uint32_t saddr, const void* gaddr) {
    asm volatile("cp.async.cg.shared.global [%0],[%1],16;" :: "r"(saddr), "l"(gaddr));
}
#define CP_COMMIT() asm volatile("cp.async.commit_group;" ::: "memory")
#define CP_WAIT(n)  asm volatile("cp.async.wait_group %0;" :: "n"(n) : "memory")

// ---------------- device globals ----------------
__device__ __align__(16) float g_gi [25165824];       // pass0: xh*wh + bias
__device__ __align__(16) float g_giB[25165824];       // pass1: xh*wl
__device__ __align__(16) float g_giC[25165824];       // pass2: xl*wh
__device__ __align__(16) __nv_bfloat16 g_xh[8192 * 4096];
__device__ __align__(16) __nv_bfloat16 g_xl[8192 * 4096];
__device__ __align__(16) __nv_bfloat16 g_wh[3072 * 4096];
__device__ __align__(16) __nv_bfloat16 g_wl[3072 * 4096];
__device__ __align__(16) float g_hring[NSLOT * HB];                      // fp32 h [kq][b][4]
__device__ __align__(16) __nv_bfloat16 g_hb16[NSLOT * 2 * Bx * Hd];      // [slot][hl][b][k]
__device__ __align__(16) __nv_bfloat16 g_wlo[NHB * 16 * 1536];           // per-CTA pre-swizzled Wlo chunk tiles
__device__ __align__(16) float g_zT[Zd * Bx];
__device__ __align__(16) float g_zpreT[Zd * Bx];
__device__ __align__(16) float g_Wmd[Zd * ZH];
__device__ __align__(16) float g_Wsd[Zd * ZH];
__device__ float g_bmu2[Zd];
__device__ float g_bsig2[Zd];
__device__ unsigned g_hprog;
__device__ unsigned g_zaprog;
__device__ unsigned g_zbprog;
__device__ unsigned g_item;
__device__ unsigned g_tmdone[64];

// ---------------- prep ----------------
__global__ void prep_kernel(const float* __restrict__ Wd, const float* __restrict__ bd,
                            const float* __restrict__ Wmu, const float* __restrict__ bmu,
                            const float* __restrict__ Wsig, const float* __restrict__ bsig)
{
    int idx = blockIdx.x * blockDim.x + threadIdx.x;
    if (idx < Zd * ZH) {
        int q = idx / ZH, j = idx % ZH;
        float am = 0.f, as = 0.f;
        for (int d = 0; d < Dd; d++) {
            float wd = Wd[(size_t)d * ZH + j];
            am = fmaf(Wmu[q * Dd + d], wd, am);
            as = fmaf(Wsig[q * Dd + d], wd, as);
        }
        g_Wmd[idx] = am;
        g_Wsd[idx] = as;
    }
    if (idx < Zd) {
        float am = bmu[idx], as = bsig[idx];
        for (int d = 0; d < Dd; d++) {
            am = fmaf(Wmu[idx * Dd + d], bd[d], am);
            as = fmaf(Wsig[idx * Dd + d], bd[d], as);
        }
        g_bmu2[idx] = am;
        g_bsig2[idx] = as;
    }
    if (idx < HB) g_hring[idx] = 0.f;
    if (idx < 2 * Bx * Hd) g_hb16[idx] = __float2bfloat16_rn(0.f);   // slot 0 hi+lo
    if (idx < Zd * Bx) g_zT[idx] = 0.f;
    if (idx < 64) g_tmdone[idx] = 0u;
    if (idx == 0) { g_hprog = 0u; g_zaprog = 0u; g_zbprog = 0u; g_item = 0u; }
}

// ---------------- split conversions ----------------
__device__ __forceinline__ void split8(const float* s, __nv_bfloat16* h, __nv_bfloat16* l) {
    #pragma unroll
    for (int i = 0; i < 8; i++) {
        float v = s[i];
        __nv_bfloat16 hb = __float2bfloat16_rn(v);
        h[i] = hb;
        l[i] = __float2bfloat16_rn(v - __bfloat162float(hb));
    }
}

__global__ void __launch_bounds__(256) conv_x(const float* __restrict__ x) {
    size_t idx = ((size_t)blockIdx.x * 256 + threadIdx.x) * 8;
    int m = (int)(idx >> 12), k = (int)(idx & 4095);
    int b = m & 31, w = m >> 5;
    float s[8];
    *(float4*)(s)     = *(const float4*)(x + ((size_t)(b * Wt + w) << 12) + k);
    *(float4*)(s + 4) = *(const float4*)(x + ((size_t)(b * Wt + w) << 12) + k + 4);
    __nv_bfloat16 h[8], l[8];
    split8(s, h, l);
    *(uint4*)(g_xh + idx) = *(uint4*)h;
    *(uint4*)(g_xl + idx) = *(uint4*)l;
}

__global__ void __launch_bounds__(256) conv_w(const float* __restrict__ Wih) {
    size_t idx = ((size_t)blockIdx.x * 256 + threadIdx.x) * 8;
    float s[8];
    *(float4*)(s)     = *(const float4*)(Wih + idx);
    *(float4*)(s + 4) = *(const float4*)(Wih + idx + 4);
    __nv_bfloat16 h[8], l[8];
    split8(s, h, l);
    *(uint4*)(g_wh + idx) = *(uint4*)h;
    *(uint4*)(g_wl + idx) = *(uint4*)l;
}

// ---------------- mega kernel ----------------
#define NITEM 4608
#define STG64 32768
#define SMB_B64 16384
#define MEGA_SMEM (110 * 1024)

// h-CTA smem layout (bytes):
//   [0, 49152)         : Whi tiles, 16 chunks x 3072B (24 rows x 128B, swizzled)
//   [49152, 71680)     : 2 stages x 11264B { hhi 4096 | hlo 4096 | wlo 3072 }
//   [71680, 75776)     : C transpose buffer 32x32 fp32
#define HOFF_WHI 0
#define HOFF_STG 49152
#define STGSZ    11264
#define HOFF_C   71680

__global__ void __launch_bounds__(256, 2) mega(
    const float* __restrict__ Whh, const float* __restrict__ bhh,
    const float* __restrict__ u, const float* __restrict__ Wpnf,
    const float* __restrict__ bpnf, const float* __restrict__ noise,
    const float* __restrict__ bih, float* __restrict__ out)
{
    extern __shared__ __align__(128) char smc[];
    float* sm = (float*)smc;
    const int bk = blockIdx.x;
    const int tid = threadIdx.x;
    const int lane = tid & 31;
    const int wp = tid >> 5;

    float* out_z  = out;
    float* out_mu = out + Bx * Wt * Zd;
    float* out_lv = out + 2 * Bx * Wt * Zd;

    auto sw = [](int r, int cb) -> uint32_t {
        return (uint32_t)(r * 128 + ((cb ^ (r & 7)) << 4));
    };

    if (bk >= NHB + NZB) {
        // ================= gemm worker CTA (R12 exact) =================
        const uint32_t sbase = smem_u32(smc);
        const int wm = (wp & 3) * 32;
        const int wn = (wp >> 2) * 64;

        uint32_t aoff[2][4], boff[4][4];
        {
            int ml = wm + (lane & 15);
            #pragma unroll
            for (int mt = 0; mt < 2; mt++)
                #pragma unroll
                for (int kh = 0; kh < 4; kh++)
                    aoff[mt][kh] = sw(ml + mt * 16, kh * 2 + (lane >> 4));
            int nl = wn + ((lane >> 4) << 3) + (lane & 7);
            #pragma unroll
            for (int p = 0; p < 4; p++)
                #pragma unroll
                for (int kh = 0; kh < 4; kh++)
                    boff[p][kh] = (uint32_t)SMB_B64 + sw(nl + p * 16, kh * 2 + ((lane >> 3) & 1));
        }

        __shared__ unsigned s_item;
        for (;;) {
            __syncthreads();
            if (tid == 0) s_item = atomicAdd(&g_item, 1u);
            __syncthreads();
            unsigned j = s_item;
            if (j >= NITEM) break;
            const int tm   = j / 72;
            const int rem  = j % 72;
            const int pass = rem / 24;
            const int tn   = rem % 24;
            const __nv_bfloat16* Asrc = (pass < 2) ? g_xh : g_xl;
            const __nv_bfloat16* Bsrc = (pass == 1) ? g_wl : g_wh;

            auto load_st = [&](int it, int slot) {
                int k0 = it << 6;
                uint32_t sb = sbase + slot * STG64;
                #pragma unroll
                for (int i = 0; i < 4; i++) {
                    int idx = tid + i * 256;
                    int r = idx >> 3, cb = idx & 7;
                    cp_async16(sb + sw(r, cb), Asrc + (((size_t)(tm * 128 + r)) << 12) + k0 + cb * 8);
                }
                #pragma unroll
                for (int i = 0; i < 4; i++) {
                    int idx = tid + i * 256;
                    int r = idx >> 3, cb = idx & 7;
                    cp_async16(sb + SMB_B64 + sw(r, cb), Bsrc + (((size_t)(tn * 128 + r)) << 12) + k0 + cb * 8);
                }
                CP_COMMIT();
            };

            float acc[2][8][4];
            #pragma unroll
            for (int mt = 0; mt < 2; mt++)
                #pragma unroll
                for (int nt = 0; nt < 8; nt++)
                    #pragma unroll
                    for (int e = 0; e < 4; e++) acc[mt][nt][e] = 0.f;

            load_st(0, 0);
            load_st(1, 1);

            #pragma unroll 1
            for (int it = 0; it < 64; it++) {
                if (it >= 62) { CP_WAIT(0); } else { CP_WAIT(1); }
                __syncthreads();
                int slot = it % 3;
                uint32_t sb = sbase + slot * STG64;
                #pragma unroll
                for (int kh = 0; kh < 4; kh++) {
                    uint32_t a[2][4], b[4][4];
                    ldsm4(a[0], sb + aoff[0][kh]);
                    ldsm4(a[1], sb + aoff[1][kh]);
                    #pragma unroll
                    for (int p = 0; p < 4; p++) ldsm4(b[p], sb + boff[p][kh]);
                    #pragma unroll
                    for (int mt = 0; mt < 2; mt++)
                        #pragma unroll
                        for (int nt = 0; nt < 8; nt++)
                            mma16816(acc[mt][nt], a[mt], &b[nt >> 1][(nt & 1) * 2]);
                }
                if (it + 2 < 64) load_st(it + 2, (it + 2) % 3);
            }

            float* gout = (pass == 0) ? g_gi : ((pass == 1) ? g_giB : g_giC);
            #pragma unroll
            for (int mt = 0; mt < 2; mt++) {
                int row0 = tm * 128 + wm + mt * 16 + (lane >> 2);
                #pragma unroll
                for (int half = 0; half < 2; half++) {
                    int row = row0 + half * 8;
                    int w = row >> 5, b = row & 31;
                    float* orow = gout + (size_t)w * G3 * 32 + b;
                    #pragma unroll
                    for (int nt = 0; nt < 8; nt++) {
                        int n = tn * 128 + wn + nt * 8 + (lane & 3) * 2;
                        float bia0 = (pass == 0) ? __ldg(bih + n) : 0.f;
                        float bia1 = (pass == 0) ? __ldg(bih + n + 1) : 0.f;
                        orow[(size_t)n * 32]       = acc[mt][nt][half * 2 + 0] + bia0;
                        orow[(size_t)(n + 1) * 32] = acc[mt][nt][half * 2 + 1] + bia1;
                    }
                }
            }
            __syncthreads();
            if (tid == 0) arrive(&g_tmdone[tm]);
        }
    } else if (bk < NHB) {
        // ================= h-pipeline CTA: tensor-core GEMV, smem-staged =================
        const uint32_t sbase = smem_u32(smc);
        float* s_c = (float*)(smc + HOFF_C);           // [32 m][32 n]
        const int i0 = bk * 8;

        // --- prologue: W slice -> Whi smem tiles + Wlo pre-swizzled global ---
        for (int idx = tid; idx < 24 * 1024; idx += 256) {
            int m = idx >> 10, k = idx & 1023;         // m = g*8+u
            int g = m >> 3, uu = m & 7;
            float v = Whh[(size_t)(g * Hd + i0 + uu) * Hd + k];
            __nv_bfloat16 hi = __float2bfloat16_rn(v);
            __nv_bfloat16 lo = __float2bfloat16_rn(v - __bfloat162float(hi));
            int kc = k >> 6, kp = k & 63, cb = kp >> 3, e = kp & 7;
            uint32_t off = sw(m, cb) + e * 2;
            *(__nv_bfloat16*)(smc + HOFF_WHI + kc * 3072 + off) = hi;
            g_wlo[((size_t)bk * 16 + kc) * 1536 + (off >> 1)] = lo;
        }
        __syncthreads();

        const int i = i0 + wp;
        const float bhr = bhh[i];
        const float bhz = bhh[Hd + i];
        const float bhn = bhh[2 * Hd + i];
        const int hoff = ((i >> 2) * 32 + lane) * 4 + (i & 3);

        // warp's mn-tile: mt = wp>>2 (m rows mt*16..), nt = wp&3 (n cols nt*8..)
        const int mt = wp >> 2;
        const int nt = wp & 3;
        // A-frag offsets within a Whi/Wlo chunk tile (clamp junk rows >=24 to row 0)
        uint32_t aoffh[4];
        #pragma unroll
        for (int kh = 0; kh < 4; kh++) {
            int r = mt * 16 + (lane & 15);
            if (r >= 24) r = 0;
            aoffh[kh] = sw(r, kh * 2 + (lane >> 4));
        }
        // B-frag offsets (16-row groups, gemm pattern)
        uint32_t boffh[2][4];
        {
            int nl = ((lane >> 4) << 3) + (lane & 7);
            #pragma unroll
            for (int p = 0; p < 2; p++)
                #pragma unroll
                for (int kh = 0; kh < 4; kh++)
                    boffh[p][kh] = sw(nl + p * 16, kh * 2 + ((lane >> 3) & 1));
        }

        #pragma unroll 1
        for (int t = 0; t < Wt; t++) {
            if (tid == 0) {
                wait_ge(&g_tmdone[t >> 2], 72u);
                if (t > 0) wait_ge(&g_hprog, (unsigned)(NHB * t));
                if (t >= NSLOT) wait_ge(&g_zaprog, (unsigned)(NZB * (t - (NSLOT - 1))));
            }
            __syncthreads();

            const size_t gbase = ((size_t)t * G3) * 32;
            size_t o_r = gbase + (size_t)(0 * Hd + i) * 32 + lane;
            size_t o_z = gbase + (size_t)(1 * Hd + i) * 32 + lane;
            size_t o_n = gbase + (size_t)(2 * Hd + i) * 32 + lane;
            float gir = g_gi[o_r] + g_giB[o_r] + g_giC[o_r];
            float giz = g_gi[o_z] + g_giB[o_z] + g_giC[o_z];
            float gin = g_gi[o_n] + g_giB[o_n] + g_giC[o_n];
            float hold = ldcg_f(g_hring + (size_t)(t & (NSLOT - 1)) * HB + hoff);

            const int slot = t & (NSLOT - 1);
            const __nv_bfloat16* hb16 = g_hb16 + (size_t)slot * (2 * Bx * Hd);

            // chunk loader: hhi @ +0 (4KB), hlo @ +4096 (4KB), wlo @ +8192 (3KB)
            auto load_ch = [&](int kc, int st) {
                uint32_t sb = sbase + HOFF_STG + st * STGSZ;
                {
                    int r = tid >> 3, cb = tid & 7;        // 32 rows x 8 cb
                    cp_async16(sb + sw(r, cb), hb16 + (size_t)r * Hd + kc * 64 + cb * 8);
                    cp_async16(sb + 4096 + sw(r, cb), hb16 + (size_t)(Bx + r) * Hd + kc * 64 + cb * 8);
                }
                if (tid < 192)
                    cp_async16(sb + 8192 + tid * 16,
                               g_wlo + ((size_t)bk * 16 + kc) * 1536 + tid * 8);
                CP_COMMIT();
            };

            float acc[4] = {0.f, 0.f, 0.f, 0.f};
            load_ch(0, 0);
            load_ch(1, 1);

            #pragma unroll 1
            for (int kc = 0; kc < 16; kc++) {
                if (kc >= 14) { CP_WAIT(0); } else { CP_WAIT(1); }
                __syncthreads();
                uint32_t sb = sbase + HOFF_STG + (kc & 1) * STGSZ;
                uint32_t whibase = sbase + HOFF_WHI + kc * 3072;
                #pragma unroll
                for (int kh = 0; kh < 4; kh++) {
                    uint32_t awh[4], awl[4], bh[2][4], bl[2][4];
                    ldsm4(awh, whibase + aoffh[kh]);
                    ldsm4(awl, sb + 8192 + aoffh[kh]);
                    ldsm4(bh[0], sb + boffh[0][kh]);
                    ldsm4(bh[1], sb + boffh[1][kh]);
                    ldsm4(bl[0], sb + 4096 + boffh[0][kh]);
                    ldsm4(bl[1], sb + 4096 + boffh[1][kh]);
                    const uint32_t* bhf = &bh[nt >> 1][(nt & 1) * 2];
                    const uint32_t* blf = &bl[nt >> 1][(nt & 1) * 2];
                    mma16816(acc, awh, bhf);
                    mma16816(acc, awh, blf);
                    mma16816(acc, awl, bhf);
                }
                __syncthreads();
                if (kc + 2 < 16) load_ch(kc + 2, kc & 1);
            }

            // transpose frags via smem: warp (mt,nt) rows mt*16+(lane>>2)+8h, cols nt*8+2(lane&3)+e
            #pragma unroll
            for (int h2 = 0; h2 < 2; h2++) {
                int m = mt * 16 + (lane >> 2) + h2 * 8;
                int n = nt * 8 + 2 * (lane & 3);
                *(float2*)&s_c[m * 32 + n] = make_float2(acc[h2 * 2 + 0], acc[h2 * 2 + 1]);
            }
            __syncthreads();

            float ar = s_c[(0 * 8 + wp) * 32 + lane];
            float az = s_c[(1 * 8 + wp) * 32 + lane];
            float an = s_c[(2 * 8 + wp) * 32 + lane];
            float rg = 1.f / (1.f + expf(-(gir + ar + bhr)));
            float zg = 1.f / (1.f + expf(-(giz + az + bhz)));
            float ng = tanhf(gin + rg * (an + bhn));
            float hnew = (1.f - zg) * ng + zg * hold;

            int ns = (t + 1) & (NSLOT - 1);
            stcg_f(g_hring + (size_t)ns * HB + hoff, hnew);
            __nv_bfloat16 hi16 = __float2bfloat16_rn(hnew);
            __nv_bfloat16 lo16 = __float2bfloat16_rn(hnew - __bfloat162float(hi16));
            __nv_bfloat16* nb = g_hb16 + (size_t)ns * (2 * Bx * Hd);
            stcg_u16(nb + (size_t)lane * Hd + i, *(unsigned short*)&hi16);
            stcg_u16(nb + (size_t)(Bx + lane) * Hd + i, *(unsigned short*)&lo16);

            __syncthreads();
            if (tid == 0) arrive(&g_hprog);
        }
    } else {
        // ================= z-pipeline CTA (R12 exact + eps prefetch) =================
        const float u0 = u[0];
        const int zb = bk - NHB;
        const int q0 = zb * 8;
        float* s_wz  = sm;
        float* s_wzz = sm + 16384;
        float* s_pnf = sm + 16384 + 1600;
        float* s_red = sm + 16384 + 1600 + 832;

        for (int idx = tid; idx < 8 * ZH; idx += 256) {
            int q8 = idx / ZH, jj = idx % ZH;
            int q = q0 + q8;
            float wm = (q < Zd) ? g_Wmd[(size_t)q * ZH + jj] : 0.f;
            float ws = (q < Zd) ? g_Wsd[(size_t)q * ZH + jj] : 0.f;
            if (jj < Zd) {
                s_wzz[jj * 16 + q8 * 2 + 0] = wm;
                s_wzz[jj * 16 + q8 * 2 + 1] = ws;
            } else {
                int kk = jj - Zd;
                int kq = kk >> 2, c = kk & 3;
                s_wz[(kq * 16 + q8 * 2 + 0) * 4 + c] = wm;
                s_wz[(kq * 16 + q8 * 2 + 1) * 4 + c] = ws;
            }
        }
        for (int idx = tid; idx < 8 * Zd; idx += 256) {
            int q8 = idx / Zd, z2 = idx % Zd;
            int q = q0 + q8;
            s_pnf[q8 * 104 + z2] = (q < Zd) ? Wpnf[q * Zd + z2] : 0.f;
        }
        __syncthreads();

        const int q = q0 + wp;
        const bool qa = (q < Zd);
        const float bm2 = qa ? g_bmu2[q] : 0.f;
        const float bs2 = qa ? g_bsig2[q] : 0.f;
        const float bpq = qa ? bpnf[q] : 0.f;
        const int kq0 = wp * 32;

        #pragma unroll 1
        for (int t = 0; t < Wt; t++) {
            float eps = qa ? noise[(size_t)(t * Bx + lane) * Zd + q] : 0.f;

            if (tid == 0) {
                wait_ge(&g_hprog, (unsigned)(NHB * (t + 1)));
                if (t > 0) wait_ge(&g_zbprog, (unsigned)(NZB * t));
            }
            __syncthreads();

            float zacc[16];
            #pragma unroll
            for (int ug = 0; ug < 16; ug++) zacc[ug] = 0.f;
            for (int z2 = wp; z2 < Zd; z2 += 8) {
                float zv = ldcg_f(g_zT + z2 * 32 + lane);
                #pragma unroll
                for (int ug = 0; ug < 16; ug++)
                    zacc[ug] = fmaf(zv, s_wzz[z2 * 16 + ug], zacc[ug]);
            }

            const float* hb = g_hring + (size_t)((t + 1) & (NSLOT - 1)) * HB;
            unsigned long long acc[16];
            #pragma unroll
            for (int ug = 0; ug < 16; ug++) acc[ug] = 0ull;

            #pragma unroll 1
            for (int jb = 0; jb < 32; jb += 8) {
                ulonglong2 hv[8];
                #pragma unroll
                for (int j = 0; j < 8; j++)
                    hv[j] = ldcg_u2(hb + (size_t)((kq0 + jb + j) * 32 + lane) * 4);
                #pragma unroll
                for (int j = 0; j < 8; j++) {
                    const ulonglong2* wq = (const ulonglong2*)(s_wz + (size_t)(kq0 + jb + j) * 64);
                    #pragma unroll
                    for (int ug = 0; ug < 16; ug++) {
                        ulonglong2 w2 = wq[ug];
                        fma2(acc[ug], hv[j].x, w2.x);
                        fma2(acc[ug], hv[j].y, w2.y);
                    }
                }
            }
            #pragma unroll
            for (int ug = 0; ug < 16; ug++) {
                float2 p = unpack2(acc[ug]);
                s_red[(wp * 16 + ug) * 32 + lane] = zacc[ug] + p.x + p.y;
            }
            __syncthreads();

            float zp = 0.f;
            if (qa) {
                float m = bm2, s = bs2;
                #pragma unroll
                for (int ww = 0; ww < 8; ww++) {
                    m += s_red[(ww * 16 + wp * 2 + 0) * 32 + lane];
                    s += s_red[(ww * 16 + wp * 2 + 1) * 32 + lane];
                }
                float lv = fmaxf(s, 0.f) + log1pf(expf(-fabsf(s)));
                zp = m + expf(0.5f * lv) * eps;
                stcg_f(g_zpreT + q * 32 + lane, zp);
                out_mu[(size_t)(lane * Wt + t) * Zd + q] = m;
                out_lv[(size_t)(lane * Wt + t) * Zd + q] = lv;
            }
            __syncthreads();
            if (tid == 0) {
                arrive(&g_zaprog);
                wait_ge(&g_zaprog, (unsigned)(NZB * (t + 1)));
            }
            __syncthreads();

            if (qa) {
                const float* pnf = s_pnf + wp * 104;
                float a0 = 0.f, a1 = 0.f;
                #pragma unroll 4
                for (int z2 = 0; z2 < Zd; z2 += 2) {
                    a0 = fmaf(ldcg_f(g_zpreT + (z2 + 0) * 32 + lane), pnf[z2 + 0], a0);
                    a1 = fmaf(ldcg_f(g_zpreT + (z2 + 1) * 32 + lane), pnf[z2 + 1], a1);
                }
                float zn = zp + u0 * tanhf((a0 + a1) + bpq);
                out_z[(size_t)(lane * Wt + t) * Zd + q] = zn;
                stcg_f(g_zT + q * 32 + lane, zn);
            }
            __syncthreads();
            if (tid == 0) arrive(&g_zbprog);
        }
    }
}

// ---------------- launch ----------------
extern "C" void kernel_launch(void* const* d_in, const int* in_sizes, int n_in,
                              void* d_out, int out_size)
{
    const float* x    = (const float*)d_in[0];
    const float* Wih  = (const float*)d_in[1];
    const float* Whh  = (const float*)d_in[2];
    const float* bih  = (const float*)d_in[3];
    const float* bhh  = (const float*)d_in[4];
    const float* Wd   = (const float*)d_in[5];
    const float* bd   = (const float*)d_in[6];
    const float* Wmu  = (const float*)d_in[7];
    const float* bmu  = (const float*)d_in[8];
    const float* Wsig = (const float*)d_in[9];
    const float* bsig = (const float*)d_in[10];
    const float* u    = (const float*)d_in[11];
    const float* Wpnf = (const float*)d_in[12];
    const float* bpnf = (const float*)d_in[13];
    const float* noise= (const float*)d_in[14];
    float* out = (float*)d_out;

    cudaFuncSetAttribute(mega, cudaFuncAttributeMaxDynamicSharedMemorySize, MEGA_SMEM);

    prep_kernel<<<(Zd * ZH + 255) / 256, 256>>>(Wd, bd, Wmu, bmu, Wsig, bsig);
    conv_x<<<(8192 * 4096) / (8 * 256), 256>>>(x);
    conv_w<<<(3072 * 4096) / (8 * 256), 256>>>(Wih);
    mega<<<NCTA, 256, MEGA_SMEM>>>(Whh, bhh, u, Wpnf, bpnf, noise, bih, out);
}

// round 16
// speedup vs baseline: 1.9492x; 1.9492x over previous
#include <cuda_runtime.h>
#include <cuda_bf16.h>
#include <math.h>
#include <stdint.h>

#define Bx  32
#define Wt  256
#define IND 4096
#define Hd  1024
#define Zd  100
#define Dd  100
#define G3  3072
#define ZH  1124
#define NHB 128
#define NZB 13
#define NGW 155                      // gemm worker CTAs
#define NCTA (NHB + NZB + NGW)       // 296
#define HB  (Hd * Bx)
#define NSLOT 16

// ---------------- f32x2 packed-FMA helpers ----------------
__device__ __forceinline__ void fma2(unsigned long long& d, unsigned long long a, unsigned long long b) {
    asm("fma.rn.f32x2 %0, %1, %2, %0;" : "+l"(d) : "l"(a), "l"(b));
}
__device__ __forceinline__ float2 unpack2(unsigned long long v) {
    float2 r;
    asm("mov.b64 {%0, %1}, %2;" : "=f"(r.x), "=f"(r.y) : "l"(v));
    return r;
}

// ---------------- L2-coherent load/store + sync primitives ----------------
__device__ __forceinline__ ulonglong2 ldcg_u2(const void* p) {
    ulonglong2 v;
    asm volatile("ld.global.cg.v2.u64 {%0,%1},[%2];" : "=l"(v.x), "=l"(v.y) : "l"(p));
    return v;
}
__device__ __forceinline__ float ldcg_f(const float* p) {
    float v; asm volatile("ld.global.cg.f32 %0,[%1];" : "=f"(v) : "l"(p)); return v;
}
__device__ __forceinline__ void stcg_f(float* p, float v) {
    asm volatile("st.global.cg.f32 [%0],%1;" :: "l"(p), "f"(v));
}
__device__ __forceinline__ void arrive(unsigned* c) {
    asm volatile("red.release.gpu.global.add.u32 [%0],%1;" :: "l"(c), "r"(1u) : "memory");
}
__device__ __forceinline__ void wait_ge(const unsigned* c, unsigned target) {
    unsigned v;
    do {
        asm volatile("ld.acquire.gpu.global.u32 %0,[%1];" : "=r"(v) : "l"(c) : "memory");
    } while ((int)(v - target) < 0);
}

// ---------------- mma.sync helpers ----------------
__device__ __forceinline__ uint32_t smem_u32(const void* p) {
    uint32_t a;
    asm("{ .reg .u64 t; cvta.to.shared.u64 t, %1; cvt.u32.u64 %0, t; }" : "=r"(a) : "l"(p));
    return a;
}
__device__ __forceinline__ void ldsm4(uint32_t* r, uint32_t addr) {
    asm volatile("ldmatrix.sync.aligned.m8n8.x4.shared.b16 {%0,%1,%2,%3},[%4];"
                 : "=r"(r[0]), "=r"(r[1]), "=r"(r[2]), "=r"(r[3]) : "r"(addr));
}
__device__ __forceinline__ void mma16816(float* c, const uint32_t* a, const uint32_t* b) {
    asm volatile("mma.sync.aligned.m16n8k16.row.col.f32.bf16.bf16.f32 "
                 "{%0,%1,%2,%3},{%4,%5,%6,%7},{%8,%9},{%0,%1,%2,%3};"
                 : "+f"(c[0]), "+f"(c[1]), "+f"(c[2]), "+f"(c[3])
                 : "r"(a[0]), "r"(a[1]), "r"(a[2]), "r"(a[3]), "r"(b[0]), "r"(b[1]));
}
__device__ __forceinline__ void cp_async16(uint32_t saddr, const void* gaddr) {
    asm volatile("cp.async.cg.shared.global [%0],[%1],16;" :: "r"(saddr), "l"(gaddr));
}
#define CP_COMMIT() asm volatile("cp.async.commit_group;" ::: "memory")
#define CP_WAIT(n)  asm volatile("cp.async.wait_group %0;" :: "n"(n) : "memory")

// ---------------- device globals ----------------
__device__ __align__(16) float g_gi [25165824];       // pass0: xh*wh + bias   [W][3H][B]
__device__ __align__(16) float g_giB[25165824];       // pass1: xh*wl
__device__ __align__(16) float g_giC[25165824];       // pass2: xl*wh
__device__ __align__(16) __nv_bfloat16 g_xh[8192 * 4096];
__device__ __align__(16) __nv_bfloat16 g_xl[8192 * 4096];
__device__ __align__(16) __nv_bfloat16 g_wh[3072 * 4096];
__device__ __align__(16) __nv_bfloat16 g_wl[3072 * 4096];
__device__ __align__(16) float g_hring[NSLOT * HB];
__device__ __align__(16) float g_zT[Zd * Bx];
__device__ __align__(16) float g_zpreT[Zd * Bx];
__device__ __align__(16) float g_Wmd[Zd * ZH];
__device__ __align__(16) float g_Wsd[Zd * ZH];
__device__ float g_bmu2[Zd];
__device__ float g_bsig2[Zd];
__device__ unsigned g_hprog;
__device__ unsigned g_zaprog;
__device__ unsigned g_zbprog;
__device__ unsigned g_item;          // gemm work queue
__device__ unsigned g_tmdone[64];    // per-tm completed item count (72 = done)

// ---------------- prep ----------------
__global__ void prep_kernel(const float* __restrict__ Wd, const float* __restrict__ bd,
                            const float* __restrict__ Wmu, const float* __restrict__ bmu,
                            const float* __restrict__ Wsig, const float* __restrict__ bsig)
{
    int idx = blockIdx.x * blockDim.x + threadIdx.x;
    if (idx < Zd * ZH) {
        int q = idx / ZH, j = idx % ZH;
        float am = 0.f, as = 0.f;
        for (int d = 0; d < Dd; d++) {
            float wd = Wd[(size_t)d * ZH + j];
            am = fmaf(Wmu[q * Dd + d], wd, am);
            as = fmaf(Wsig[q * Dd + d], wd, as);
        }
        g_Wmd[idx] = am;
        g_Wsd[idx] = as;
    }
    if (idx < Zd) {
        float am = bmu[idx], as = bsig[idx];
        for (int d = 0; d < Dd; d++) {
            am = fmaf(Wmu[idx * Dd + d], bd[d], am);
            as = fmaf(Wsig[idx * Dd + d], bd[d], as);
        }
        g_bmu2[idx] = am;
        g_bsig2[idx] = as;
    }
    if (idx < HB) g_hring[idx] = 0.f;
    if (idx < Zd * Bx) g_zT[idx] = 0.f;
    if (idx < 64) g_tmdone[idx] = 0u;
    if (idx == 0) { g_hprog = 0u; g_zaprog = 0u; g_zbprog = 0u; g_item = 0u; }
}

// ---------------- split conversions ----------------
__device__ __forceinline__ void split8(const float* s, __nv_bfloat16* h, __nv_bfloat16* l) {
    #pragma unroll
    for (int i = 0; i < 8; i++) {
        float v = s[i];
        __nv_bfloat16 hb = __float2bfloat16_rn(v);
        h[i] = hb;
        l[i] = __float2bfloat16_rn(v - __bfloat162float(hb));
    }
}

__global__ void __launch_bounds__(256) conv_x(const float* __restrict__ x) {
    size_t idx = ((size_t)blockIdx.x * 256 + threadIdx.x) * 8;
    int m = (int)(idx >> 12), k = (int)(idx & 4095);
    int b = m & 31, w = m >> 5;
    float s[8];
    *(float4*)(s)     = *(const float4*)(x + ((size_t)(b * Wt + w) << 12) + k);
    *(float4*)(s + 4) = *(const float4*)(x + ((size_t)(b * Wt + w) << 12) + k + 4);
    __nv_bfloat16 h[8], l[8];
    split8(s, h, l);
    *(uint4*)(g_xh + idx) = *(uint4*)h;
    *(uint4*)(g_xl + idx) = *(uint4*)l;
}

__global__ void __launch_bounds__(256) conv_w(const float* __restrict__ Wih) {
    size_t idx = ((size_t)blockIdx.x * 256 + threadIdx.x) * 8;
    float s[8];
    *(float4*)(s)     = *(const float4*)(Wih + idx);
    *(float4*)(s + 4) = *(const float4*)(Wih + idx + 4);
    __nv_bfloat16 h[8], l[8];
    split8(s, h, l);
    *(uint4*)(g_wh + idx) = *(uint4*)h;
    *(uint4*)(g_wl + idx) = *(uint4*)l;
}

// ---------------- mega kernel: 128 h-CTAs + 13 z-CTAs + 155 gemm workers ----------------
#define NITEM 4608
#define STG64 32768
#define SMB_B64 16384
#define MEGA_SMEM (110 * 1024)       // 110KB -> 2 CTAs/SM

__global__ void __launch_bounds__(256, 2) mega(
    const float* __restrict__ Whh, const float* __restrict__ bhh,
    const float* __restrict__ u, const float* __restrict__ Wpnf,
    const float* __restrict__ bpnf, const float* __restrict__ noise,
    const float* __restrict__ bih, float* __restrict__ out)
{
    extern __shared__ __align__(128) char smc[];
    float* sm = (float*)smc;
    const int bk = blockIdx.x;
    const int tid = threadIdx.x;
    const int lane = tid & 31;
    const int wp = tid >> 5;

    float* out_z  = out;
    float* out_mu = out + Bx * Wt * Zd;
    float* out_lv = out + 2 * Bx * Wt * Zd;

    if (bk >= NHB + NZB) {
        // ================= gemm worker CTA =================
        const uint32_t sbase = smem_u32(smc);
        const int wm = (wp & 3) * 32;
        const int wn = (wp >> 2) * 64;

        auto sw = [](int r, int cb) -> uint32_t {
            return (uint32_t)(r * 128 + ((cb ^ (r & 7)) << 4));
        };
        uint32_t aoff[2][4], boff[4][4];
        {
            int ml = wm + (lane & 15);
            #pragma unroll
            for (int mt = 0; mt < 2; mt++)
                #pragma unroll
                for (int kh = 0; kh < 4; kh++)
                    aoff[mt][kh] = sw(ml + mt * 16, kh * 2 + (lane >> 4));
            int nl = wn + ((lane >> 4) << 3) + (lane & 7);
            #pragma unroll
            for (int p = 0; p < 4; p++)
                #pragma unroll
                for (int kh = 0; kh < 4; kh++)
                    boff[p][kh] = (uint32_t)SMB_B64 + sw(nl + p * 16, kh * 2 + ((lane >> 3) & 1));
        }

        __shared__ unsigned s_item;
        for (;;) {
            __syncthreads();                 // protect smem slots + s_item from prev item
            if (tid == 0) s_item = atomicAdd(&g_item, 1u);
            __syncthreads();
            unsigned j = s_item;
            if (j >= NITEM) break;
            // tm-major item order: tm = j/72; within: pass = rem/24, tn = rem%24
            const int tm   = j / 72;
            const int rem  = j % 72;
            const int pass = rem / 24;
            const int tn   = rem % 24;
            const __nv_bfloat16* Asrc = (pass < 2) ? g_xh : g_xl;
            const __nv_bfloat16* Bsrc = (pass == 1) ? g_wl : g_wh;

            auto load_st = [&](int it, int slot) {
                int k0 = it << 6;
                uint32_t sb = sbase + slot * STG64;
                #pragma unroll
                for (int i = 0; i < 4; i++) {
                    int idx = tid + i * 256;
                    int r = idx >> 3, cb = idx & 7;
                    cp_async16(sb + sw(r, cb), Asrc + (((size_t)(tm * 128 + r)) << 12) + k0 + cb * 8);
                }
                #pragma unroll
                for (int i = 0; i < 4; i++) {
                    int idx = tid + i * 256;
                    int r = idx >> 3, cb = idx & 7;
                    cp_async16(sb + SMB_B64 + sw(r, cb), Bsrc + (((size_t)(tn * 128 + r)) << 12) + k0 + cb * 8);
                }
                CP_COMMIT();
            };

            float acc[2][8][4];
            #pragma unroll
            for (int mt = 0; mt < 2; mt++)
                #pragma unroll
                for (int nt = 0; nt < 8; nt++)
                    #pragma unroll
                    for (int e = 0; e < 4; e++) acc[mt][nt][e] = 0.f;

            load_st(0, 0);
            load_st(1, 1);

            #pragma unroll 1
            for (int it = 0; it < 64; it++) {
                if (it >= 62) { CP_WAIT(0); } else { CP_WAIT(1); }
                __syncthreads();
                int slot = it % 3;
                uint32_t sb = sbase + slot * STG64;
                #pragma unroll
                for (int kh = 0; kh < 4; kh++) {
                    uint32_t a[2][4], b[4][4];
                    ldsm4(a[0], sb + aoff[0][kh]);
                    ldsm4(a[1], sb + aoff[1][kh]);
                    #pragma unroll
                    for (int p = 0; p < 4; p++) ldsm4(b[p], sb + boff[p][kh]);
                    #pragma unroll
                    for (int mt = 0; mt < 2; mt++)
                        #pragma unroll
                        for (int nt = 0; nt < 8; nt++)
                            mma16816(acc[mt][nt], a[mt], &b[nt >> 1][(nt & 1) * 2]);
                }
                if (it + 2 < 64) load_st(it + 2, (it + 2) % 3);
            }

            float* gout = (pass == 0) ? g_gi : ((pass == 1) ? g_giB : g_giC);
            #pragma unroll
            for (int mt = 0; mt < 2; mt++) {
                int row0 = tm * 128 + wm + mt * 16 + (lane >> 2);
                #pragma unroll
                for (int half = 0; half < 2; half++) {
                    int row = row0 + half * 8;
                    int w = row >> 5, b = row & 31;
                    float* orow = gout + (size_t)w * G3 * 32 + b;
                    #pragma unroll
                    for (int nt = 0; nt < 8; nt++) {
                        int n = tn * 128 + wn + nt * 8 + (lane & 3) * 2;
                        float bia0 = (pass == 0) ? __ldg(bih + n) : 0.f;
                        float bia1 = (pass == 0) ? __ldg(bih + n + 1) : 0.f;
                        orow[(size_t)n * 32]       = acc[mt][nt][half * 2 + 0] + bia0;
                        orow[(size_t)(n + 1) * 32] = acc[mt][nt][half * 2 + 1] + bia1;
                    }
                }
            }
            __syncthreads();                 // all stores done (CTA-wide) before signal
            if (tid == 0) arrive(&g_tmdone[tm]);
        }
    } else if (bk < NHB) {
        // ================= h-pipeline CTA (R12 structure + cached tmdone skip) =================
        float* s_whh = sm;                   // 24*1024 floats = 96KB
        float* s_red = sm + 24 * 1024;       // [4][24][32] = 12KB
        const int i0 = bk * 8;

        for (int idx = tid; idx < 24576; idx += 256) {
            int c = idx & 3;
            int rest = idx >> 2;
            int g = rest % 3;
            int t2 = rest / 3;
            int uu = t2 & 7;
            int kq = t2 >> 3;
            s_whh[idx] = Whh[(size_t)(g * Hd + i0 + uu) * Hd + kq * 4 + c];
        }
        __syncthreads();

        const int i = i0 + wp;
        const float bhr = bhh[i];
        const float bhz = bhh[Hd + i];
        const float bhn = bhh[2 * Hd + i];
        const int hoff = ((i >> 2) * 32 + lane) * 4 + (i & 3);
        const int kq0 = wp * 32;
        unsigned tmw = 0u;                   // last tm known complete (tid0 only meaningful)

        #pragma unroll 1
        for (int t = 0; t < Wt; t++) {
            if (tid == 0) {
                unsigned tmq = (unsigned)(t >> 2);
                if (tmq >= tmw) { wait_ge(&g_tmdone[tmq], 72u); tmw = tmq + 1u; }
                if (t > 0) wait_ge(&g_hprog, (unsigned)(NHB * t));
                if (t >= NSLOT) wait_ge(&g_zaprog, (unsigned)(NZB * (t - (NSLOT - 1))));
            }
            __syncthreads();

            const size_t gbase = ((size_t)t * G3) * 32;
            size_t o_r = gbase + (size_t)(0 * Hd + i) * 32 + lane;
            size_t o_z = gbase + (size_t)(1 * Hd + i) * 32 + lane;
            size_t o_n = gbase + (size_t)(2 * Hd + i) * 32 + lane;
            float gir = g_gi[o_r] + g_giB[o_r] + g_giC[o_r];
            float giz = g_gi[o_z] + g_giB[o_z] + g_giC[o_z];
            float gin = g_gi[o_n] + g_giB[o_n] + g_giC[o_n];
            const float* hb = g_hring + (size_t)(t & (NSLOT - 1)) * HB;
            float hold = ldcg_f(hb + hoff);

            unsigned long long acc[24];
            #pragma unroll
            for (int ug = 0; ug < 24; ug++) acc[ug] = 0ull;

            #pragma unroll 1
            for (int jb = 0; jb < 32; jb += 8) {
                ulonglong2 hv[8];
                #pragma unroll
                for (int j = 0; j < 8; j++)
                    hv[j] = ldcg_u2(hb + (size_t)((kq0 + jb + j) * 32 + lane) * 4);
                #pragma unroll
                for (int j = 0; j < 8; j++) {
                    const ulonglong2* wq = (const ulonglong2*)(s_whh + (size_t)(kq0 + jb + j) * 96);
                    #pragma unroll
                    for (int ug = 0; ug < 24; ug++) {
                        ulonglong2 w2 = wq[ug];
                        fma2(acc[ug], hv[j].x, w2.x);
                        fma2(acc[ug], hv[j].y, w2.y);
                    }
                }
            }
            float part[24];
            #pragma unroll
            for (int ug = 0; ug < 24; ug++) {
                float2 p = unpack2(acc[ug]);
                part[ug] = p.x + p.y;
            }
            // two-phase reduce into [4][24][32]
            if (wp >= 4) {
                #pragma unroll
                for (int ug = 0; ug < 24; ug++)
                    s_red[((wp - 4) * 24 + ug) * 32 + lane] = part[ug];
            }
            __syncthreads();
            if (wp < 4) {
                #pragma unroll
                for (int ug = 0; ug < 24; ug++)
                    s_red[(wp * 24 + ug) * 32 + lane] += part[ug];
            }
            __syncthreads();

            float ar = 0.f, az = 0.f, an = 0.f;
            #pragma unroll
            for (int w2 = 0; w2 < 4; w2++) {
                ar += s_red[(w2 * 24 + wp * 3 + 0) * 32 + lane];
                az += s_red[(w2 * 24 + wp * 3 + 1) * 32 + lane];
                an += s_red[(w2 * 24 + wp * 3 + 2) * 32 + lane];
            }
            float rg = 1.f / (1.f + expf(-(gir + ar + bhr)));
            float zg = 1.f / (1.f + expf(-(giz + az + bhz)));
            float ng = tanhf(gin + rg * (an + bhn));
            float hnew = (1.f - zg) * ng + zg * hold;
            stcg_f(g_hring + (size_t)((t + 1) & (NSLOT - 1)) * HB + hoff, hnew);

            __syncthreads();
            if (tid == 0) arrive(&g_hprog);
        }
    } else {
        // ================= z-pipeline CTA (R12 + eps prefetch) =================
        const float u0 = u[0];
        const int zb = bk - NHB;
        const int q0 = zb * 8;
        float* s_wz  = sm;
        float* s_wzz = sm + 16384;
        float* s_pnf = sm + 16384 + 1600;
        float* s_red = sm + 16384 + 1600 + 832;

        for (int idx = tid; idx < 8 * ZH; idx += 256) {
            int q8 = idx / ZH, jj = idx % ZH;
            int q = q0 + q8;
            float wm = (q < Zd) ? g_Wmd[(size_t)q * ZH + jj] : 0.f;
            float ws = (q < Zd) ? g_Wsd[(size_t)q * ZH + jj] : 0.f;
            if (jj < Zd) {
                s_wzz[jj * 16 + q8 * 2 + 0] = wm;
                s_wzz[jj * 16 + q8 * 2 + 1] = ws;
            } else {
                int kk = jj - Zd;
                int kq = kk >> 2, c = kk & 3;
                s_wz[(kq * 16 + q8 * 2 + 0) * 4 + c] = wm;
                s_wz[(kq * 16 + q8 * 2 + 1) * 4 + c] = ws;
            }
        }
        for (int idx = tid; idx < 8 * Zd; idx += 256) {
            int q8 = idx / Zd, z2 = idx % Zd;
            int q = q0 + q8;
            s_pnf[q8 * 104 + z2] = (q < Zd) ? Wpnf[q * Zd + z2] : 0.f;
        }
        __syncthreads();

        const int q = q0 + wp;
        const bool qa = (q < Zd);
        const float bm2 = qa ? g_bmu2[q] : 0.f;
        const float bs2 = qa ? g_bsig2[q] : 0.f;
        const float bpq = qa ? bpnf[q] : 0.f;
        const int kq0 = wp * 32;

        #pragma unroll 1
        for (int t = 0; t < Wt; t++) {
            float eps = qa ? noise[(size_t)(t * Bx + lane) * Zd + q] : 0.f;

            if (tid == 0) {
                wait_ge(&g_hprog, (unsigned)(NHB * (t + 1)));
                if (t > 0) wait_ge(&g_zbprog, (unsigned)(NZB * t));
            }
            __syncthreads();

            float zacc[16];
            #pragma unroll
            for (int ug = 0; ug < 16; ug++) zacc[ug] = 0.f;
            for (int z2 = wp; z2 < Zd; z2 += 8) {
                float zv = ldcg_f(g_zT + z2 * 32 + lane);
                #pragma unroll
                for (int ug = 0; ug < 16; ug++)
                    zacc[ug] = fmaf(zv, s_wzz[z2 * 16 + ug], zacc[ug]);
            }

            const float* hb = g_hring + (size_t)((t + 1) & (NSLOT - 1)) * HB;
            unsigned long long acc[16];
            #pragma unroll
            for (int ug = 0; ug < 16; ug++) acc[ug] = 0ull;

            #pragma unroll 1
            for (int jb = 0; jb < 32; jb += 8) {
                ulonglong2 hv[8];
                #pragma unroll
                for (int j = 0; j < 8; j++)
                    hv[j] = ldcg_u2(hb + (size_t)((kq0 + jb + j) * 32 + lane) * 4);
                #pragma unroll
                for (int j = 0; j < 8; j++) {
                    const ulonglong2* wq = (const ulonglong2*)(s_wz + (size_t)(kq0 + jb + j) * 64);
                    #pragma unroll
                    for (int ug = 0; ug < 16; ug++) {
                        ulonglong2 w2 = wq[ug];
                        fma2(acc[ug], hv[j].x, w2.x);
                        fma2(acc[ug], hv[j].y, w2.y);
                    }
                }
            }
            #pragma unroll
            for (int ug = 0; ug < 16; ug++) {
                float2 p = unpack2(acc[ug]);
                s_red[(wp * 16 + ug) * 32 + lane] = zacc[ug] + p.x + p.y;
            }
            __syncthreads();

            float zp = 0.f;
            if (qa) {
                float m = bm2, s = bs2;
                #pragma unroll
                for (int ww = 0; ww < 8; ww++) {
                    m += s_red[(ww * 16 + wp * 2 + 0) * 32 + lane];
                    s += s_red[(ww * 16 + wp * 2 + 1) * 32 + lane];
                }
                float lv = fmaxf(s, 0.f) + log1pf(expf(-fabsf(s)));
                zp = m + expf(0.5f * lv) * eps;
                stcg_f(g_zpreT + q * 32 + lane, zp);
                out_mu[(size_t)(lane * Wt + t) * Zd + q] = m;
                out_lv[(size_t)(lane * Wt + t) * Zd + q] = lv;
            }
            __syncthreads();
            if (tid == 0) {
                arrive(&g_zaprog);
                wait_ge(&g_zaprog, (unsigned)(NZB * (t + 1)));
            }
            __syncthreads();

            if (qa) {
                const float* pnf = s_pnf + wp * 104;
                float a0 = 0.f, a1 = 0.f;
                #pragma unroll 4
                for (int z2 = 0; z2 < Zd; z2 += 2) {
                    a0 = fmaf(ldcg_f(g_zpreT + (z2 + 0) * 32 + lane), pnf[z2 + 0], a0);
                    a1 = fmaf(ldcg_f(g_zpreT + (z2 + 1) * 32 + lane), pnf[z2 + 1], a1);
                }
                float zn = zp + u0 * tanhf((a0 + a1) + bpq);
                out_z[(size_t)(lane * Wt + t) * Zd + q] = zn;
                stcg_f(g_zT + q * 32 + lane, zn);
            }
            __syncthreads();
            if (tid == 0) arrive(&g_zbprog);
        }
    }
}

// ---------------- launch ----------------
extern "C" void kernel_launch(void* const* d_in, const int* in_sizes, int n_in,
                              void* d_out, int out_size)
{
    const float* x    = (const float*)d_in[0];
    const float* Wih  = (const float*)d_in[1];
    const float* Whh  = (const float*)d_in[2];
    const float* bih  = (const float*)d_in[3];
    const float* bhh  = (const float*)d_in[4];
    const float* Wd   = (const float*)d_in[5];
    const float* bd   = (const float*)d_in[6];
    const float* Wmu  = (const float*)d_in[7];
    const float* bmu  = (const float*)d_in[8];
    const float* Wsig = (const float*)d_in[9];
    const float* bsig = (const float*)d_in[10];
    const float* u    = (const float*)d_in[11];
    const float* Wpnf = (const float*)d_in[12];
    const float* bpnf = (const float*)d_in[13];
    const float* noise= (const float*)d_in[14];
    float* out = (float*)d_out;

    cudaFuncSetAttribute(mega, cudaFuncAttributeMaxDynamicSharedMemorySize, MEGA_SMEM);

    prep_kernel<<<(Zd * ZH + 255) / 256, 256>>>(Wd, bd, Wmu, bmu, Wsig, bsig);
    conv_x<<<(8192 * 4096) / (8 * 256), 256>>>(x);
    conv_w<<<(3072 * 4096) / (8 * 256), 256>>>(Wih);
    mega<<<NCTA, 256, MEGA_SMEM>>>(Whh, bhh, u, Wpnf, bpnf, noise, bih, out);
}

// round 17
// speedup vs baseline: 2.0558x; 1.0547x over previous
#include <cuda_runtime.h>
#include <cuda_bf16.h>
#include <math.h>
#include <stdint.h>

#define Bx  32
#define Wt  256
#define IND 4096
#define Hd  1024
#define Zd  100
#define Dd  100
#define G3  3072
#define ZH  1124
#define NHB 128
#define NZB 13
#define NGW 155                      // gemm worker CTAs
#define NCTA (NHB + NZB + NGW)       // 296
#define HB  (Hd * Bx)
#define NSLOT 16

// ---------------- f32x2 packed-FMA helpers ----------------
__device__ __forceinline__ void fma2(unsigned long long& d, unsigned long long a, unsigned long long b) {
    asm("fma.rn.f32x2 %0, %1, %2, %0;" : "+l"(d) : "l"(a), "l"(b));
}
__device__ __forceinline__ float2 unpack2(unsigned long long v) {
    float2 r;
    asm("mov.b64 {%0, %1}, %2;" : "=f"(r.x), "=f"(r.y) : "l"(v));
    return r;
}

// ---------------- L2-coherent load/store + sync primitives ----------------
__device__ __forceinline__ ulonglong2 ldcg_u2(const void* p) {
    ulonglong2 v;
    asm volatile("ld.global.cg.v2.u64 {%0,%1},[%2];" : "=l"(v.x), "=l"(v.y) : "l"(p));
    return v;
}
__device__ __forceinline__ float ldcg_f(const float* p) {
    float v; asm volatile("ld.global.cg.f32 %0,[%1];" : "=f"(v) : "l"(p)); return v;
}
__device__ __forceinline__ void stcg_f(float* p, float v) {
    asm volatile("st.global.cg.f32 [%0],%1;" :: "l"(p), "f"(v));
}
__device__ __forceinline__ void arrive(unsigned* c) {
    asm volatile("red.release.gpu.global.add.u32 [%0],%1;" :: "l"(c), "r"(1u) : "memory");
}
__device__ __forceinline__ void wait_ge(const unsigned* c, unsigned target) {
    unsigned v;
    do {
        asm volatile("ld.acquire.gpu.global.u32 %0,[%1];" : "=r"(v) : "l"(c) : "memory");
    } while ((int)(v - target) < 0);
}

// ---------------- mma.sync helpers ----------------
__device__ __forceinline__ uint32_t smem_u32(const void* p) {
    uint32_t a;
    asm("{ .reg .u64 t; cvta.to.shared.u64 t, %1; cvt.u32.u64 %0, t; }" : "=r"(a) : "l"(p));
    return a;
}
__device__ __forceinline__ void ldsm4(uint32_t* r, uint32_t addr) {
    asm volatile("ldmatrix.sync.aligned.m8n8.x4.shared.b16 {%0,%1,%2,%3},[%4];"
                 : "=r"(r[0]), "=r"(r[1]), "=r"(r[2]), "=r"(r[3]) : "r"(addr));
}
__device__ __forceinline__ void mma16816(float* c, const uint32_t* a, const uint32_t* b) {
    asm volatile("mma.sync.aligned.m16n8k16.row.col.f32.bf16.bf16.f32 "
                 "{%0,%1,%2,%3},{%4,%5,%6,%7},{%8,%9},{%0,%1,%2,%3};"
                 : "+f"(c[0]), "+f"(c[1]), "+f"(c[2]), "+f"(c[3])
                 : "r"(a[0]), "r"(a[1]), "r"(a[2]), "r"(a[3]), "r"(b[0]), "r"(b[1]));
}
__device__ __forceinline__ void cp_async16(uint32_t saddr, const void* gaddr) {
    asm volatile("cp.async.cg.shared.global [%0],[%1],16;" :: "r"(saddr), "l"(gaddr));
}
#define CP_COMMIT() asm volatile("cp.async.commit_group;" ::: "memory")
#define CP_WAIT(n)  asm volatile("cp.async.wait_group %0;" :: "n"(n) : "memory")

// ---------------- device globals ----------------
__device__ __align__(16) float g_gi [25165824];       // pass0: xh*wh + bias   [W][3H][B]
__device__ __align__(16) float g_giB[25165824];       // pass1: xh*wl
__device__ __align__(16) float g_giC[25165824];       // pass2: xl*wh
__device__ __align__(16) __nv_bfloat16 g_xh[8192 * 4096];
__device__ __align__(16) __nv_bfloat16 g_xl[8192 * 4096];
__device__ __align__(16) __nv_bfloat16 g_wh[3072 * 4096];
__device__ __align__(16) __nv_bfloat16 g_wl[3072 * 4096];
__device__ __align__(16) float g_hring[NSLOT * HB];
__device__ __align__(16) float g_zT[Zd * Bx];
__device__ __align__(16) float g_zpreT[Zd * Bx];
__device__ __align__(16) float g_Wmd[Zd * ZH];
__device__ __align__(16) float g_Wsd[Zd * ZH];
__device__ float g_bmu2[Zd];
__device__ float g_bsig2[Zd];
__device__ unsigned g_hprog;
__device__ unsigned g_zaprog;
__device__ unsigned g_zbprog;
__device__ unsigned g_item;          // gemm work queue
__device__ unsigned g_tmdone[64];    // per-tm completed item count (72 = done)

// ---------------- prep ----------------
__global__ void prep_kernel(const float* __restrict__ Wd, const float* __restrict__ bd,
                            const float* __restrict__ Wmu, const float* __restrict__ bmu,
                            const float* __restrict__ Wsig, const float* __restrict__ bsig)
{
    int idx = blockIdx.x * blockDim.x + threadIdx.x;
    if (idx < Zd * ZH) {
        int q = idx / ZH, j = idx % ZH;
        float am = 0.f, as = 0.f;
        for (int d = 0; d < Dd; d++) {
            float wd = Wd[(size_t)d * ZH + j];
            am = fmaf(Wmu[q * Dd + d], wd, am);
            as = fmaf(Wsig[q * Dd + d], wd, as);
        }
        g_Wmd[idx] = am;
        g_Wsd[idx] = as;
    }
    if (idx < Zd) {
        float am = bmu[idx], as = bsig[idx];
        for (int d = 0; d < Dd; d++) {
            am = fmaf(Wmu[idx * Dd + d], bd[d], am);
            as = fmaf(Wsig[idx * Dd + d], bd[d], as);
        }
        g_bmu2[idx] = am;
        g_bsig2[idx] = as;
    }
    if (idx < HB) g_hring[idx] = 0.f;
    if (idx < Zd * Bx) g_zT[idx] = 0.f;
    if (idx < 64) g_tmdone[idx] = 0u;
    if (idx == 0) { g_hprog = 0u; g_zaprog = 0u; g_zbprog = 0u; g_item = 0u; }
}

// ---------------- split conversions ----------------
__device__ __forceinline__ void split8(const float* s, __nv_bfloat16* h, __nv_bfloat16* l) {
    #pragma unroll
    for (int i = 0; i < 8; i++) {
        float v = s[i];
        __nv_bfloat16 hb = __float2bfloat16_rn(v);
        h[i] = hb;
        l[i] = __float2bfloat16_rn(v - __bfloat162float(hb));
    }
}

__global__ void __launch_bounds__(256) conv_x(const float* __restrict__ x) {
    size_t idx = ((size_t)blockIdx.x * 256 + threadIdx.x) * 8;
    int m = (int)(idx >> 12), k = (int)(idx & 4095);
    int b = m & 31, w = m >> 5;
    float s[8];
    *(float4*)(s)     = *(const float4*)(x + ((size_t)(b * Wt + w) << 12) + k);
    *(float4*)(s + 4) = *(const float4*)(x + ((size_t)(b * Wt + w) << 12) + k + 4);
    __nv_bfloat16 h[8], l[8];
    split8(s, h, l);
    *(uint4*)(g_xh + idx) = *(uint4*)h;
    *(uint4*)(g_xl + idx) = *(uint4*)l;
}

__global__ void __launch_bounds__(256) conv_w(const float* __restrict__ Wih) {
    size_t idx = ((size_t)blockIdx.x * 256 + threadIdx.x) * 8;
    float s[8];
    *(float4*)(s)     = *(const float4*)(Wih + idx);
    *(float4*)(s + 4) = *(const float4*)(Wih + idx + 4);
    __nv_bfloat16 h[8], l[8];
    split8(s, h, l);
    *(uint4*)(g_wh + idx) = *(uint4*)h;
    *(uint4*)(g_wl + idx) = *(uint4*)l;
}

// ---------------- mega kernel: 128 h-CTAs + 13 z-CTAs + 155 gemm workers ----------------
#define NITEM 4608
#define STG64 32768
#define SMB_B64 16384
#define MEGA_SMEM (110 * 1024)       // 110KB -> 2 CTAs/SM

__global__ void __launch_bounds__(256, 2) mega(
    const float* __restrict__ Whh, const float* __restrict__ bhh,
    const float* __restrict__ u, const float* __restrict__ Wpnf,
    const float* __restrict__ bpnf, const float* __restrict__ noise,
    const float* __restrict__ bih, float* __restrict__ out)
{
    extern __shared__ __align__(128) char smc[];
    float* sm = (float*)smc;
    const int bk = blockIdx.x;
    const int tid = threadIdx.x;
    const int lane = tid & 31;
    const int wp = tid >> 5;

    float* out_z  = out;
    float* out_mu = out + Bx * Wt * Zd;
    float* out_lv = out + 2 * Bx * Wt * Zd;

    if (bk >= NHB + NZB) {
        // ================= gemm worker CTA (R12 exact) =================
        const uint32_t sbase = smem_u32(smc);
        const int wm = (wp & 3) * 32;
        const int wn = (wp >> 2) * 64;

        auto sw = [](int r, int cb) -> uint32_t {
            return (uint32_t)(r * 128 + ((cb ^ (r & 7)) << 4));
        };
        uint32_t aoff[2][4], boff[4][4];
        {
            int ml = wm + (lane & 15);
            #pragma unroll
            for (int mt = 0; mt < 2; mt++)
                #pragma unroll
                for (int kh = 0; kh < 4; kh++)
                    aoff[mt][kh] = sw(ml + mt * 16, kh * 2 + (lane >> 4));
            int nl = wn + ((lane >> 4) << 3) + (lane & 7);
            #pragma unroll
            for (int p = 0; p < 4; p++)
                #pragma unroll
                for (int kh = 0; kh < 4; kh++)
                    boff[p][kh] = (uint32_t)SMB_B64 + sw(nl + p * 16, kh * 2 + ((lane >> 3) & 1));
        }

        __shared__ unsigned s_item;
        for (;;) {
            __syncthreads();
            if (tid == 0) s_item = atomicAdd(&g_item, 1u);
            __syncthreads();
            unsigned j = s_item;
            if (j >= NITEM) break;
            const int tm   = j / 72;
            const int rem  = j % 72;
            const int pass = rem / 24;
            const int tn   = rem % 24;
            const __nv_bfloat16* Asrc = (pass < 2) ? g_xh : g_xl;
            const __nv_bfloat16* Bsrc = (pass == 1) ? g_wl : g_wh;

            auto load_st = [&](int it, int slot) {
                int k0 = it << 6;
                uint32_t sb = sbase + slot * STG64;
                #pragma unroll
                for (int i = 0; i < 4; i++) {
                    int idx = tid + i * 256;
                    int r = idx >> 3, cb = idx & 7;
                    cp_async16(sb + sw(r, cb), Asrc + (((size_t)(tm * 128 + r)) << 12) + k0 + cb * 8);
                }
                #pragma unroll
                for (int i = 0; i < 4; i++) {
                    int idx = tid + i * 256;
                    int r = idx >> 3, cb = idx & 7;
                    cp_async16(sb + SMB_B64 + sw(r, cb), Bsrc + (((size_t)(tn * 128 + r)) << 12) + k0 + cb * 8);
                }
                CP_COMMIT();
            };

            float acc[2][8][4];
            #pragma unroll
            for (int mt = 0; mt < 2; mt++)
                #pragma unroll
                for (int nt = 0; nt < 8; nt++)
                    #pragma unroll
                    for (int e = 0; e < 4; e++) acc[mt][nt][e] = 0.f;

            load_st(0, 0);
            load_st(1, 1);

            #pragma unroll 1
            for (int it = 0; it < 64; it++) {
                if (it >= 62) { CP_WAIT(0); } else { CP_WAIT(1); }
                __syncthreads();
                int slot = it % 3;
                uint32_t sb = sbase + slot * STG64;
                #pragma unroll
                for (int kh = 0; kh < 4; kh++) {
                    uint32_t a[2][4], b[4][4];
                    ldsm4(a[0], sb + aoff[0][kh]);
                    ldsm4(a[1], sb + aoff[1][kh]);
                    #pragma unroll
                    for (int p = 0; p < 4; p++) ldsm4(b[p], sb + boff[p][kh]);
                    #pragma unroll
                    for (int mt = 0; mt < 2; mt++)
                        #pragma unroll
                        for (int nt = 0; nt < 8; nt++)
                            mma16816(acc[mt][nt], a[mt], &b[nt >> 1][(nt & 1) * 2]);
                }
                if (it + 2 < 64) load_st(it + 2, (it + 2) % 3);
            }

            float* gout = (pass == 0) ? g_gi : ((pass == 1) ? g_giB : g_giC);
            #pragma unroll
            for (int mt = 0; mt < 2; mt++) {
                int row0 = tm * 128 + wm + mt * 16 + (lane >> 2);
                #pragma unroll
                for (int half = 0; half < 2; half++) {
                    int row = row0 + half * 8;
                    int w = row >> 5, b = row & 31;
                    float* orow = gout + (size_t)w * G3 * 32 + b;
                    #pragma unroll
                    for (int nt = 0; nt < 8; nt++) {
                        int n = tn * 128 + wn + nt * 8 + (lane & 3) * 2;
                        float bia0 = (pass == 0) ? __ldg(bih + n) : 0.f;
                        float bia1 = (pass == 0) ? __ldg(bih + n + 1) : 0.f;
                        orow[(size_t)n * 32]       = acc[mt][nt][half * 2 + 0] + bia0;
                        orow[(size_t)(n + 1) * 32] = acc[mt][nt][half * 2 + 1] + bia1;
                    }
                }
            }
            __syncthreads();
            if (tid == 0) arrive(&g_tmdone[tm]);
        }
    } else if (bk < NHB) {
        // ================= h-pipeline CTA (R12 + fully-unrolled jb loop) =================
        float* s_whh = sm;                   // 24*1024 floats = 96KB
        float* s_red = sm + 24 * 1024;       // [4][24][32] = 12KB
        const int i0 = bk * 8;

        for (int idx = tid; idx < 24576; idx += 256) {
            int c = idx & 3;
            int rest = idx >> 2;
            int g = rest % 3;
            int t2 = rest / 3;
            int uu = t2 & 7;
            int kq = t2 >> 3;
            s_whh[idx] = Whh[(size_t)(g * Hd + i0 + uu) * Hd + kq * 4 + c];
        }
        __syncthreads();

        const int i = i0 + wp;
        const float bhr = bhh[i];
        const float bhz = bhh[Hd + i];
        const float bhn = bhh[2 * Hd + i];
        const int hoff = ((i >> 2) * 32 + lane) * 4 + (i & 3);
        const int kq0 = wp * 32;

        #pragma unroll 1
        for (int t = 0; t < Wt; t++) {
            if (tid == 0) {
                wait_ge(&g_tmdone[t >> 2], 72u);
                if (t > 0) wait_ge(&g_hprog, (unsigned)(NHB * t));
                if (t >= NSLOT) wait_ge(&g_zaprog, (unsigned)(NZB * (t - (NSLOT - 1))));
            }
            __syncthreads();

            const size_t gbase = ((size_t)t * G3) * 32;
            size_t o_r = gbase + (size_t)(0 * Hd + i) * 32 + lane;
            size_t o_z = gbase + (size_t)(1 * Hd + i) * 32 + lane;
            size_t o_n = gbase + (size_t)(2 * Hd + i) * 32 + lane;
            float gir = g_gi[o_r] + g_giB[o_r] + g_giC[o_r];
            float giz = g_gi[o_z] + g_giB[o_z] + g_giC[o_z];
            float gin = g_gi[o_n] + g_giB[o_n] + g_giC[o_n];
            const float* hb = g_hring + (size_t)(t & (NSLOT - 1)) * HB;
            float hold = ldcg_f(hb + hoff);

            unsigned long long acc[24];
            #pragma unroll
            for (int ug = 0; ug < 24; ug++) acc[ug] = 0ull;

            #pragma unroll
            for (int jb = 0; jb < 32; jb += 8) {
                ulonglong2 hv[8];
                #pragma unroll
                for (int j = 0; j < 8; j++)
                    hv[j] = ldcg_u2(hb + (size_t)((kq0 + jb + j) * 32 + lane) * 4);
                #pragma unroll
                for (int j = 0; j < 8; j++) {
                    const ulonglong2* wq = (const ulonglong2*)(s_whh + (size_t)(kq0 + jb + j) * 96);
                    #pragma unroll
                    for (int ug = 0; ug < 24; ug++) {
                        ulonglong2 w2 = wq[ug];
                        fma2(acc[ug], hv[j].x, w2.x);
                        fma2(acc[ug], hv[j].y, w2.y);
                    }
                }
            }
            float part[24];
            #pragma unroll
            for (int ug = 0; ug < 24; ug++) {
                float2 p = unpack2(acc[ug]);
                part[ug] = p.x + p.y;
            }
            // two-phase reduce into [4][24][32]
            if (wp >= 4) {
                #pragma unroll
                for (int ug = 0; ug < 24; ug++)
                    s_red[((wp - 4) * 24 + ug) * 32 + lane] = part[ug];
            }
            __syncthreads();
            if (wp < 4) {
                #pragma unroll
                for (int ug = 0; ug < 24; ug++)
                    s_red[(wp * 24 + ug) * 32 + lane] += part[ug];
            }
            __syncthreads();

            float ar = 0.f, az = 0.f, an = 0.f;
            #pragma unroll
            for (int w2 = 0; w2 < 4; w2++) {
                ar += s_red[(w2 * 24 + wp * 3 + 0) * 32 + lane];
                az += s_red[(w2 * 24 + wp * 3 + 1) * 32 + lane];
                an += s_red[(w2 * 24 + wp * 3 + 2) * 32 + lane];
            }
            float rg = 1.f / (1.f + expf(-(gir + ar + bhr)));
            float zg = 1.f / (1.f + expf(-(giz + az + bhz)));
            float ng = tanhf(gin + rg * (an + bhn));
            float hnew = (1.f - zg) * ng + zg * hold;
            stcg_f(g_hring + (size_t)((t + 1) & (NSLOT - 1)) * HB + hoff, hnew);

            __syncthreads();
            if (tid == 0) arrive(&g_hprog);
        }
    } else {
        // ================= z-pipeline CTA (R12 + fully-unrolled jb loop) =================
        const float u0 = u[0];
        const int zb = bk - NHB;
        const int q0 = zb * 8;
        float* s_wz  = sm;
        float* s_wzz = sm + 16384;
        float* s_pnf = sm + 16384 + 1600;
        float* s_red = sm + 16384 + 1600 + 832;

        for (int idx = tid; idx < 8 * ZH; idx += 256) {
            int q8 = idx / ZH, jj = idx % ZH;
            int q = q0 + q8;
            float wm = (q < Zd) ? g_Wmd[(size_t)q * ZH + jj] : 0.f;
            float ws = (q < Zd) ? g_Wsd[(size_t)q * ZH + jj] : 0.f;
            if (jj < Zd) {
                s_wzz[jj * 16 + q8 * 2 + 0] = wm;
                s_wzz[jj * 16 + q8 * 2 + 1] = ws;
            } else {
                int kk = jj - Zd;
                int kq = kk >> 2, c = kk & 3;
                s_wz[(kq * 16 + q8 * 2 + 0) * 4 + c] = wm;
                s_wz[(kq * 16 + q8 * 2 + 1) * 4 + c] = ws;
            }
        }
        for (int idx = tid; idx < 8 * Zd; idx += 256) {
            int q8 = idx / Zd, z2 = idx % Zd;
            int q = q0 + q8;
            s_pnf[q8 * 104 + z2] = (q < Zd) ? Wpnf[q * Zd + z2] : 0.f;
        }
        __syncthreads();

        const int q = q0 + wp;
        const bool qa = (q < Zd);
        const float bm2 = qa ? g_bmu2[q] : 0.f;
        const float bs2 = qa ? g_bsig2[q] : 0.f;
        const float bpq = qa ? bpnf[q] : 0.f;
        const int kq0 = wp * 32;

        #pragma unroll 1
        for (int t = 0; t < Wt; t++) {
            float eps = qa ? noise[(size_t)(t * Bx + lane) * Zd + q] : 0.f;

            if (tid == 0) {
                wait_ge(&g_hprog, (unsigned)(NHB * (t + 1)));
                if (t > 0) wait_ge(&g_zbprog, (unsigned)(NZB * t));
            }
            __syncthreads();

            float zacc[16];
            #pragma unroll
            for (int ug = 0; ug < 16; ug++) zacc[ug] = 0.f;
            for (int z2 = wp; z2 < Zd; z2 += 8) {
                float zv = ldcg_f(g_zT + z2 * 32 + lane);
                #pragma unroll
                for (int ug = 0; ug < 16; ug++)
                    zacc[ug] = fmaf(zv, s_wzz[z2 * 16 + ug], zacc[ug]);
            }

            const float* hb = g_hring + (size_t)((t + 1) & (NSLOT - 1)) * HB;
            unsigned long long acc[16];
            #pragma unroll
            for (int ug = 0; ug < 16; ug++) acc[ug] = 0ull;

            #pragma unroll
            for (int jb = 0; jb < 32; jb += 8) {
                ulonglong2 hv[8];
                #pragma unroll
                for (int j = 0; j < 8; j++)
                    hv[j] = ldcg_u2(hb + (size_t)((kq0 + jb + j) * 32 + lane) * 4);
                #pragma unroll
                for (int j = 0; j < 8; j++) {
                    const ulonglong2* wq = (const ulonglong2*)(s_wz + (size_t)(kq0 + jb + j) * 64);
                    #pragma unroll
                    for (int ug = 0; ug < 16; ug++) {
                        ulonglong2 w2 = wq[ug];
                        fma2(acc[ug], hv[j].x, w2.x);
                        fma2(acc[ug], hv[j].y, w2.y);
                    }
                }
            }
            #pragma unroll
            for (int ug = 0; ug < 16; ug++) {
                float2 p = unpack2(acc[ug]);
                s_red[(wp * 16 + ug) * 32 + lane] = zacc[ug] + p.x + p.y;
            }
            __syncthreads();

            float zp = 0.f;
            if (qa) {
                float m = bm2, s = bs2;
                #pragma unroll
                for (int ww = 0; ww < 8; ww++) {
                    m += s_red[(ww * 16 + wp * 2 + 0) * 32 + lane];
                    s += s_red[(ww * 16 + wp * 2 + 1) * 32 + lane];
                }
                float lv = fmaxf(s, 0.f) + log1pf(expf(-fabsf(s)));
                zp = m + expf(0.5f * lv) * eps;
                stcg_f(g_zpreT + q * 32 + lane, zp);
                out_mu[(size_t)(lane * Wt + t) * Zd + q] = m;
                out_lv[(size_t)(lane * Wt + t) * Zd + q] = lv;
            }
            __syncthreads();
            if (tid == 0) {
                arrive(&g_zaprog);
                wait_ge(&g_zaprog, (unsigned)(NZB * (t + 1)));
            }
            __syncthreads();

            if (qa) {
                const float* pnf = s_pnf + wp * 104;
                float a0 = 0.f, a1 = 0.f;
                #pragma unroll 4
                for (int z2 = 0; z2 < Zd; z2 += 2) {
                    a0 = fmaf(ldcg_f(g_zpreT + (z2 + 0) * 32 + lane), pnf[z2 + 0], a0);
                    a1 = fmaf(ldcg_f(g_zpreT + (z2 + 1) * 32 + lane), pnf[z2 + 1], a1);
                }
                float zn = zp + u0 * tanhf((a0 + a1) + bpq);
                out_z[(size_t)(lane * Wt + t) * Zd + q] = zn;
                stcg_f(g_zT + q * 32 + lane, zn);
            }
            __syncthreads();
            if (tid == 0) arrive(&g_zbprog);
        }
    }
}

// ---------------- launch ----------------
extern "C" void kernel_launch(void* const* d_in, const int* in_sizes, int n_in,
                              void* d_out, int out_size)
{
    const float* x    = (const float*)d_in[0];
    const float* Wih  = (const float*)d_in[1];
    const float* Whh  = (const float*)d_in[2];
    const float* bih  = (const float*)d_in[3];
    const float* bhh  = (const float*)d_in[4];
    const float* Wd   = (const float*)d_in[5];
    const float* bd   = (const float*)d_in[6];
    const float* Wmu  = (const float*)d_in[7];
    const float* bmu  = (const float*)d_in[8];
    const float* Wsig = (const float*)d_in[9];
    const float* bsig = (const float*)d_in[10];
    const float* u    = (const float*)d_in[11];
    const float* Wpnf = (const float*)d_in[12];
    const float* bpnf = (const float*)d_in[13];
    const float* noise= (const float*)d_in[14];
    float* out = (float*)d_out;

    cudaFuncSetAttribute(mega, cudaFuncAttributeMaxDynamicSharedMemorySize, MEGA_SMEM);

    prep_kernel<<<(Zd * ZH + 255) / 256, 256>>>(Wd, bd, Wmu, bmu, Wsig, bsig);
    conv_x<<<(8192 * 4096) / (8 * 256), 256>>>(x);
    conv_w<<<(3072 * 4096) / (8 * 256), 256>>>(Wih);
    mega<<<NCTA, 256, MEGA_SMEM>>>(Whh, bhh, u, Wpnf, bpnf, noise, bih, out);
}